// round 13
// baseline (speedup 1.0000x reference)
#include <cuda_runtime.h>
#include <math.h>

// Problem constants (fixed by setup_inputs)
#define BB 2
#define NN 16384
#define MQ 4096
#define C1 128
#define C2 256
#define FC 384          // feature channels (128 + 256)
#define VC 387          // 3 coords + 384 features (logical per-query channels)
#define GC 1024         // global feature channels
#define CT 1411         // total channels
#define VCOLS 1124      // output columns whose window touches per-query channels
#define GCOLS (MQ - VCOLS)   // 2972 columns depending only on global feats

#define TPTS 2048       // kNN smem tile points (32 KB of float4)
#define KQW 3           // queries per warp (LDS-traffic / latency-hiding middle)
#define KWARPS 8        // warps per kNN block
#define KQB (KQW * KWARPS)   // 24 queries per block
#define BPB 171         // ceil(MQ / KQB); last block clamps 8 dup queries
#define FULL 0xffffffffu

// mega-kernel block ranges
#define KNNB (BB * BPB)                              // 342 kNN blocks
#define TRN  (NN / 32)                               // 512 transpose n-tiles
#define TRC  (FC / 32)                               // 12 transpose c-tiles
#define TRB  (TRN * TRC * BB)                        // 12288 transpose blocks
#define GPB  ((BB * GCOLS + 255) / 256)              // 24 gpool blocks

// ---------------- scratch (static device memory; no allocations) -------------
__device__ float  g_w [BB * MQ * 3];       // normalized Gaussian weights
__device__ int    g_i [BB * MQ * 3];       // final kNN indices
__device__ float  g_ft[(long)BB * NN * FC];// transposed features [b][n][c]
__device__ float4 g_grow[BB][GCOLS / 4];   // per-batch pooled global segment

#define FINF __int_as_float(0x7f800000)

__device__ __forceinline__ void ins3(float t, int n,
                                     float& d0, float& d1, float& d2,
                                     int& i0, int& i1, int& i2) {
    if (t < d1) {
        d2 = d1; i2 = i1;
        if (t < d0) { d1 = d0; i1 = i0; d0 = t; i0 = n; }
        else        { d1 = t;  i1 = n; }
    } else { d2 = t; i2 = n; }
}

// ---------------- kernel A: mega (kNN | transpose | gpool by block range) ----
union SmemU {
    float4 tile4[TPTS];          // kNN point tile
    float  t32[32][33];          // transpose tile
};

__global__ void __launch_bounds__(256)
mega_kernel(const float* __restrict__ P,  const float* __restrict__ Q,
            const float* __restrict__ F1, const float* __restrict__ F2,
            const float* __restrict__ G) {
    __shared__ SmemU su;

    // ======================= path 1: kNN ===================================
    if (blockIdx.x < KNNB) {
        int b    = blockIdx.x / BPB;
        int q0   = (blockIdx.x % BPB) * KQB;
        int wid  = threadIdx.x >> 5;
        int lane = threadIdx.x & 31;

        float qx[KQW], qy[KQW], qz[KQW];
        int   mq[KQW];
#pragma unroll
        for (int g = 0; g < KQW; g++) {
            int m = q0 + wid * KQW + g;
            mq[g] = (m < MQ) ? m : (MQ - 1);       // clamp (dup writes benign)
            qx[g] = Q[b * 3 * MQ + mq[g]];
            qy[g] = Q[b * 3 * MQ + MQ + mq[g]];
            qz[g] = Q[b * 3 * MQ + 2 * MQ + mq[g]];
        }

        float d0a[KQW], d1a[KQW], d2a[KQW];
        int   i0a[KQW], i1a[KQW], i2a[KQW];
#pragma unroll
        for (int g = 0; g < KQW; g++) {
            d0a[g] = FINF; d1a[g] = FINF; d2a[g] = FINF;
            i0a[g] = 0;    i1a[g] = 0;    i2a[g] = 0;
        }

        const float* Pb = P + b * 3 * NN;

#define RESCAN(tv, v, g)                                               \
    {                                                                  \
        unsigned bal = __ballot_sync(FULL, (tv) < d2a[g]);             \
        while (bal) {                                                  \
            int L = __ffs(bal) - 1; bal &= bal - 1;                    \
            float val = __shfl_sync(FULL, (tv), L);                    \
            if (val < d2a[g])                                          \
                ins3(val, tb + r + (v) * 32 + L,                       \
                     d0a[g], d1a[g], d2a[g], i0a[g], i1a[g], i2a[g]);  \
        }                                                              \
    }

        for (int tb = 0; tb < NN; tb += TPTS) {
            // inline preprocessing: (-2x,-2y,-2z,p2) built from P
            for (int j = threadIdx.x; j < TPTS; j += 256) {
                int n = tb + j;
                float x = Pb[n], y = Pb[NN + n], z = Pb[2 * NN + n];
                su.tile4[j] = make_float4(-2.f * x, -2.f * y, -2.f * z,
                                          x * x + y * y + z * z);
            }
            __syncthreads();

            for (int r = 0; r < TPTS; r += 128) {      // 128 points per round
                float4 p0 = su.tile4[r + lane];
                float4 p1 = su.tile4[r + 32 + lane];
                float4 p2 = su.tile4[r + 64 + lane];
                float4 p3 = su.tile4[r + 96 + lane];
                float t0g[KQW], t1g[KQW], t2g[KQW], t3g[KQW];
                bool hit = false;
#pragma unroll
                for (int g = 0; g < KQW; g++) {
                    float t0 = fmaf(qz[g], p0.z, fmaf(qy[g], p0.y, fmaf(qx[g], p0.x, p0.w)));
                    float t1 = fmaf(qz[g], p1.z, fmaf(qy[g], p1.y, fmaf(qx[g], p1.x, p1.w)));
                    float t2 = fmaf(qz[g], p2.z, fmaf(qy[g], p2.y, fmaf(qx[g], p2.x, p2.w)));
                    float t3 = fmaf(qz[g], p3.z, fmaf(qy[g], p3.y, fmaf(qx[g], p3.x, p3.w)));
                    t0g[g] = t0; t1g[g] = t1; t2g[g] = t2; t3g[g] = t3;
                    float mn = fminf(fminf(t0, t1), fminf(t2, t3));
                    hit |= (mn < d2a[g]);
                }
                if (__any_sync(FULL, hit)) {           // one vote per round
#pragma unroll
                    for (int g = 0; g < KQW; g++) {
                        RESCAN(t0g[g], 0, g);
                        RESCAN(t1g[g], 1, g);
                        RESCAN(t2g[g], 2, g);
                        RESCAN(t3g[g], 3, g);
                    }
                }
            }
            __syncthreads();
        }
#undef RESCAN

        if (lane == 0) {
#pragma unroll
            for (int g = 0; g < KQW; g++) {
                int t = b * MQ + mq[g];
                float e1 = expf(-0.5f * (d1a[g] - d0a[g]));
                float e2 = expf(-0.5f * (d2a[g] - d0a[g]));
                float inv = 1.0f / (1.0f + e1 + e2);
                g_w[t * 3]     = inv;
                g_w[t * 3 + 1] = e1 * inv;
                g_w[t * 3 + 2] = e2 * inv;
                g_i[t * 3]     = i0a[g];
                g_i[t * 3 + 1] = i1a[g];
                g_i[t * 3 + 2] = i2a[g];
            }
        }
        return;
    }

    // ======================= path 2: feature transpose ======================
    if (blockIdx.x < KNNB + TRB) {
        int t  = blockIdx.x - KNNB;
        int n0 = (t % TRN) * 32;
        int cb = (t / TRN) % TRC;
        int b  = t / (TRN * TRC);
        const float* F;
        int C, c0, coff;
        if (cb < C1 / 32) { F = F1; C = C1; c0 = cb * 32;             coff = 0;  }
        else              { F = F2; C = C2; c0 = (cb - C1 / 32) * 32; coff = C1; }
        int tx = threadIdx.x & 31;
        int ty = threadIdx.x >> 5;

#pragma unroll
        for (int r = ty; r < 32; r += 8)
            su.t32[r][tx] = F[((long)(b * C + c0 + r)) * NN + n0 + tx];
        __syncthreads();
#pragma unroll
        for (int r = ty; r < 32; r += 8) {
            int n = n0 + r, c = c0 + tx;
            g_ft[((long)(b * NN + n)) * FC + coff + c] = su.t32[tx][r];
        }
        return;
    }

    // ======================= path 3: gpool ==================================
    {
        int t = (blockIdx.x - KNNB - TRB) * 256 + threadIdx.x;
        if (t >= BB * GCOLS) return;
        int b = t / GCOLS;
        int i = VCOLS + t % GCOLS;
        int st = (i * CT) >> 12;
        int en = ((i + 1) * CT + 4095) >> 12;
        float a = __ldg(&G[b * GC + st - VC]);
        if (en - st == 2) a = fmaxf(a, __ldg(&G[b * GC + st + 1 - VC]));
        ((float*)g_grow[b])[i - VCOLS] = a;
    }
}

// ---------------- kernel B: fused interp + adaptive max pool + output -------
#define RPB 8
__global__ void __launch_bounds__(256) pool_kernel(const float* __restrict__ Q,
                                                   const float* __restrict__ G,
                                                   float* __restrict__ out) {
    __shared__ float sv[RPB][VC + 1];   // [0..2]=coords, [3..386]=feat, [VC]=sg0
    __shared__ unsigned meta[VCOLS];    // st | (st2 << 16), branchless dual-max
    __shared__ float sw[RPB][3];
    __shared__ int   si[RPB][3];

    int blk = blockIdx.x;                 // 0 .. B*MQ/RPB - 1
    int b   = blk / (MQ / RPB);
    int m0  = (blk % (MQ / RPB)) * RPB;
    float sg0 = G[b * GC];                // only global channel reachable in i<VCOLS

    // precompute window metadata once per block (reused by all RPB rows)
    for (int i = threadIdx.x; i < VCOLS; i += 256) {
        unsigned st = (i * CT) >> 12;
        unsigned en = ((i + 1) * CT + 4095) >> 12;
        unsigned st2 = (en - st == 2) ? st + 1 : st;   // st2==VC handled via sv[.][VC]
        meta[i] = st | (st2 << 16);
    }
    if (threadIdx.x < RPB * 3) {
        int r = threadIdx.x / 3, k = threadIdx.x % 3;
        sw[r][k] = g_w[(b * MQ + m0 + r) * 3 + k];
        si[r][k] = g_i[(b * MQ + m0 + r) * 3 + k];
        sv[r][k] = Q[(b * 3 + k) * MQ + m0 + r];
    }
    if (threadIdx.x >= 32 && threadIdx.x < 32 + RPB)
        sv[threadIdx.x - 32][VC] = sg0;
    __syncthreads();

    // interpolation: RPB rows x 96 float4 tasks; gathers are contiguous 1536B rows
    for (int idx = threadIdx.x; idx < RPB * (FC / 4); idx += 256) {
        int r  = idx / (FC / 4);
        int c4 = idx % (FC / 4);
        float w0 = sw[r][0], w1 = sw[r][1], w2 = sw[r][2];
        const float4* f0 = (const float4*)(g_ft + ((long)(b * NN + si[r][0])) * FC);
        const float4* f1 = (const float4*)(g_ft + ((long)(b * NN + si[r][1])) * FC);
        const float4* f2 = (const float4*)(g_ft + ((long)(b * NN + si[r][2])) * FC);
        float4 a = f0[c4], bb = f1[c4], cc = f2[c4];
        float* dst = &sv[r][3 + c4 * 4];
        dst[0] = w0 * a.x + w1 * bb.x + w2 * cc.x;
        dst[1] = w0 * a.y + w1 * bb.y + w2 * cc.y;
        dst[2] = w0 * a.z + w1 * bb.z + w2 * cc.z;
        dst[3] = w0 * a.w + w1 * bb.w + w2 * cc.w;
    }
    __syncthreads();

    const float4* gr = g_grow[b];
#pragma unroll 2
    for (int r = 0; r < RPB; r++) {
        float* orow = out + ((long)(b * MQ + m0 + r)) * MQ;
        // segment A: columns [0, VCOLS): branchless dual-max via meta
        for (int q = threadIdx.x; q < VCOLS / 4; q += 256) {
            float4 o;
            float* op = (float*)&o;
#pragma unroll
            for (int u = 0; u < 4; u++) {
                unsigned m = meta[q * 4 + u];
                op[u] = fmaxf(sv[r][m & 0xffff], sv[r][m >> 16]);
            }
            ((float4*)orow)[q] = o;
        }
        // segment B: columns [VCOLS, MQ): batch-constant, vectorized copy
        float4* od = (float4*)(orow + VCOLS);
        for (int q = threadIdx.x; q < GCOLS / 4; q += 256)
            od[q] = gr[q];
    }
}

// ---------------- launch -----------------------------------------------------
extern "C" void kernel_launch(void* const* d_in, const int* in_sizes, int n_in,
                              void* d_out, int out_size) {
    const float* P  = (const float*)d_in[0];   // original_pts [B,3,N]
    const float* Q  = (const float*)d_in[1];   // query_pts    [B,3,M]
    const float* F1 = (const float*)d_in[2];   // local_feat1  [B,128,N]
    const float* F2 = (const float*)d_in[3];   // local_feat2  [B,256,N]
    const float* G  = (const float*)d_in[4];   // global_feats [B,1024]
    float* out = (float*)d_out;                // [B,M,M]

    mega_kernel<<<KNNB + TRB + GPB, 256>>>(P, Q, F1, F2, G);
    pool_kernel<<<BB * MQ / RPB, 256>>>(Q, G, out);
}

// round 14
// speedup vs baseline: 1.0371x; 1.0371x over previous
#include <cuda_runtime.h>
#include <math.h>

// Problem constants (fixed by setup_inputs)
#define BB 2
#define NN 16384
#define MQ 4096
#define C1 128
#define C2 256
#define FC 384          // feature channels (128 + 256)
#define VC 387          // 3 coords + 384 features (logical per-query channels)
#define GC 1024         // global feature channels
#define CT 1411         // total channels
#define VCOLS 1124      // output columns whose window touches per-query channels
#define GCOLS (MQ - VCOLS)   // 2972 columns depending only on global feats

#define TPTS 2048       // kNN smem tile points (32 KB of float4)
#define PPT (TPTS / 256)     // 8 points per thread per tile
#define KQW 2           // queries per warp (empirical optimum)
#define KWARPS 8        // warps per kNN block
#define KQB (KQW * KWARPS)   // 16 queries per block
#define FULL 0xffffffffu

// mega-kernel block ranges
#define KNNB (BB * (MQ / KQB))                       // 512 kNN blocks
#define TRN  (NN / 32)                               // 512 transpose n-tiles
#define TRC  (FC / 32)                               // 12 transpose c-tiles
#define TRB  (TRN * TRC * BB)                        // 12288 transpose blocks
#define GPB  ((BB * GCOLS + 255) / 256)              // 24 gpool blocks

// ---------------- scratch (static device memory; no allocations) -------------
__device__ float  g_w [BB * MQ * 3];       // normalized Gaussian weights
__device__ int    g_i [BB * MQ * 3];       // final kNN indices
__device__ float  g_ft[(long)BB * NN * FC];// transposed features [b][n][c]
__device__ float4 g_grow[BB][GCOLS / 4];   // per-batch pooled global segment

#define FINF __int_as_float(0x7f800000)

__device__ __forceinline__ void ins3(float t, int n,
                                     float& d0, float& d1, float& d2,
                                     int& i0, int& i1, int& i2) {
    if (t < d1) {
        d2 = d1; i2 = i1;
        if (t < d0) { d1 = d0; i1 = i0; d0 = t; i0 = n; }
        else        { d1 = t;  i1 = n; }
    } else { d2 = t; i2 = n; }
}

// ---------------- kernel A: mega (kNN | transpose | gpool by block range) ----
union SmemU {
    float4 tile4[TPTS];          // kNN point tile
    float  t32[32][33];          // transpose tile
};

__global__ void __launch_bounds__(256)
mega_kernel(const float* __restrict__ P,  const float* __restrict__ Q,
            const float* __restrict__ F1, const float* __restrict__ F2,
            const float* __restrict__ G) {
    __shared__ SmemU su;

    // ======================= path 1: kNN ===================================
    if (blockIdx.x < KNNB) {
        const int bpb = MQ / KQB;                 // 256 query-blocks per batch
        int b    = blockIdx.x / bpb;
        int q0   = (blockIdx.x % bpb) * KQB;
        int wid  = threadIdx.x >> 5;
        int lane = threadIdx.x & 31;

        float qx[KQW], qy[KQW], qz[KQW];
        int   mq[KQW];
#pragma unroll
        for (int g = 0; g < KQW; g++) {
            mq[g] = q0 + wid * KQW + g;
            qx[g] = Q[b * 3 * MQ + mq[g]];
            qy[g] = Q[b * 3 * MQ + MQ + mq[g]];
            qz[g] = Q[b * 3 * MQ + 2 * MQ + mq[g]];
        }

        float d0a[KQW], d1a[KQW], d2a[KQW];
        int   i0a[KQW], i1a[KQW], i2a[KQW];
#pragma unroll
        for (int g = 0; g < KQW; g++) {
            d0a[g] = FINF; d1a[g] = FINF; d2a[g] = FINF;
            i0a[g] = 0;    i1a[g] = 0;    i2a[g] = 0;
        }

        const float* Pb = P + b * 3 * NN;

        // prefetch tile 0 raw coordinates into registers
        float px[PPT], py[PPT], pz[PPT];
#pragma unroll
        for (int k = 0; k < PPT; k++) {
            int n = k * 256 + threadIdx.x;
            px[k] = Pb[n]; py[k] = Pb[NN + n]; pz[k] = Pb[2 * NN + n];
        }

#define RESCAN(tv, v, g)                                               \
    {                                                                  \
        unsigned bal = __ballot_sync(FULL, (tv) < d2a[g]);             \
        while (bal) {                                                  \
            int L = __ffs(bal) - 1; bal &= bal - 1;                    \
            float val = __shfl_sync(FULL, (tv), L);                    \
            if (val < d2a[g])                                          \
                ins3(val, tb + r + (v) * 32 + L,                       \
                     d0a[g], d1a[g], d2a[g], i0a[g], i1a[g], i2a[g]);  \
        }                                                              \
    }

        for (int tb = 0; tb < NN; tb += TPTS) {
            // store prefetched tile (preprocessed) to smem
#pragma unroll
            for (int k = 0; k < PPT; k++) {
                su.tile4[k * 256 + threadIdx.x] =
                    make_float4(-2.f * px[k], -2.f * py[k], -2.f * pz[k],
                                px[k] * px[k] + py[k] * py[k] + pz[k] * pz[k]);
            }
            __syncthreads();

            // prefetch NEXT tile raw coords (LDG latency hides under rounds)
            if (tb + TPTS < NN) {
#pragma unroll
                for (int k = 0; k < PPT; k++) {
                    int n = tb + TPTS + k * 256 + threadIdx.x;
                    px[k] = Pb[n]; py[k] = Pb[NN + n]; pz[k] = Pb[2 * NN + n];
                }
            }

            for (int r = 0; r < TPTS; r += 128) {      // 128 points per round
                float4 p0 = su.tile4[r + lane];
                float4 p1 = su.tile4[r + 32 + lane];
                float4 p2 = su.tile4[r + 64 + lane];
                float4 p3 = su.tile4[r + 96 + lane];
                float t0g[KQW], t1g[KQW], t2g[KQW], t3g[KQW];
                bool hit = false;
#pragma unroll
                for (int g = 0; g < KQW; g++) {
                    float t0 = fmaf(qz[g], p0.z, fmaf(qy[g], p0.y, fmaf(qx[g], p0.x, p0.w)));
                    float t1 = fmaf(qz[g], p1.z, fmaf(qy[g], p1.y, fmaf(qx[g], p1.x, p1.w)));
                    float t2 = fmaf(qz[g], p2.z, fmaf(qy[g], p2.y, fmaf(qx[g], p2.x, p2.w)));
                    float t3 = fmaf(qz[g], p3.z, fmaf(qy[g], p3.y, fmaf(qx[g], p3.x, p3.w)));
                    t0g[g] = t0; t1g[g] = t1; t2g[g] = t2; t3g[g] = t3;
                    float mn = fminf(fminf(t0, t1), fminf(t2, t3));
                    hit |= (mn < d2a[g]);
                }
                if (__any_sync(FULL, hit)) {           // one vote per round
#pragma unroll
                    for (int g = 0; g < KQW; g++) {
                        RESCAN(t0g[g], 0, g);
                        RESCAN(t1g[g], 1, g);
                        RESCAN(t2g[g], 2, g);
                        RESCAN(t3g[g], 3, g);
                    }
                }
            }
            __syncthreads();
        }
#undef RESCAN

        if (lane == 0) {
#pragma unroll
            for (int g = 0; g < KQW; g++) {
                int t = b * MQ + mq[g];
                float e1 = expf(-0.5f * (d1a[g] - d0a[g]));
                float e2 = expf(-0.5f * (d2a[g] - d0a[g]));
                float inv = 1.0f / (1.0f + e1 + e2);
                g_w[t * 3]     = inv;
                g_w[t * 3 + 1] = e1 * inv;
                g_w[t * 3 + 2] = e2 * inv;
                g_i[t * 3]     = i0a[g];
                g_i[t * 3 + 1] = i1a[g];
                g_i[t * 3 + 2] = i2a[g];
            }
        }
        return;
    }

    // ======================= path 2: feature transpose ======================
    if (blockIdx.x < KNNB + TRB) {
        int t  = blockIdx.x - KNNB;
        int n0 = (t % TRN) * 32;
        int cb = (t / TRN) % TRC;
        int b  = t / (TRN * TRC);
        const float* F;
        int C, c0, coff;
        if (cb < C1 / 32) { F = F1; C = C1; c0 = cb * 32;             coff = 0;  }
        else              { F = F2; C = C2; c0 = (cb - C1 / 32) * 32; coff = C1; }
        int tx = threadIdx.x & 31;
        int ty = threadIdx.x >> 5;

#pragma unroll
        for (int r = ty; r < 32; r += 8)
            su.t32[r][tx] = F[((long)(b * C + c0 + r)) * NN + n0 + tx];
        __syncthreads();
#pragma unroll
        for (int r = ty; r < 32; r += 8) {
            int n = n0 + r, c = c0 + tx;
            g_ft[((long)(b * NN + n)) * FC + coff + c] = su.t32[tx][r];
        }
        return;
    }

    // ======================= path 3: gpool ==================================
    {
        int t = (blockIdx.x - KNNB - TRB) * 256 + threadIdx.x;
        if (t >= BB * GCOLS) return;
        int b = t / GCOLS;
        int i = VCOLS + t % GCOLS;
        int st = (i * CT) >> 12;
        int en = ((i + 1) * CT + 4095) >> 12;
        float a = __ldg(&G[b * GC + st - VC]);
        if (en - st == 2) a = fmaxf(a, __ldg(&G[b * GC + st + 1 - VC]));
        ((float*)g_grow[b])[i - VCOLS] = a;
    }
}

// ---------------- kernel B: fused interp + adaptive max pool + output -------
#define RPB 8
__global__ void __launch_bounds__(256) pool_kernel(const float* __restrict__ Q,
                                                   const float* __restrict__ G,
                                                   float* __restrict__ out) {
    __shared__ float sv[RPB][VC + 1];   // [0..2]=coords, [3..386]=feat, [VC]=sg0
    __shared__ unsigned meta[VCOLS];    // st | (st2 << 16), branchless dual-max
    __shared__ float sw[RPB][3];
    __shared__ int   si[RPB][3];

    int blk = blockIdx.x;                 // 0 .. B*MQ/RPB - 1
    int b   = blk / (MQ / RPB);
    int m0  = (blk % (MQ / RPB)) * RPB;
    float sg0 = G[b * GC];                // only global channel reachable in i<VCOLS

    // precompute window metadata once per block (reused by all RPB rows)
    for (int i = threadIdx.x; i < VCOLS; i += 256) {
        unsigned st = (i * CT) >> 12;
        unsigned en = ((i + 1) * CT + 4095) >> 12;
        unsigned st2 = (en - st == 2) ? st + 1 : st;   // st2==VC handled via sv[.][VC]
        meta[i] = st | (st2 << 16);
    }
    if (threadIdx.x < RPB * 3) {
        int r = threadIdx.x / 3, k = threadIdx.x % 3;
        sw[r][k] = g_w[(b * MQ + m0 + r) * 3 + k];
        si[r][k] = g_i[(b * MQ + m0 + r) * 3 + k];
        sv[r][k] = Q[(b * 3 + k) * MQ + m0 + r];
    }
    if (threadIdx.x >= 32 && threadIdx.x < 32 + RPB)
        sv[threadIdx.x - 32][VC] = sg0;
    __syncthreads();

    // interpolation: RPB rows x 96 float4 tasks; gathers are contiguous 1536B rows
    for (int idx = threadIdx.x; idx < RPB * (FC / 4); idx += 256) {
        int r  = idx / (FC / 4);
        int c4 = idx % (FC / 4);
        float w0 = sw[r][0], w1 = sw[r][1], w2 = sw[r][2];
        const float4* f0 = (const float4*)(g_ft + ((long)(b * NN + si[r][0])) * FC);
        const float4* f1 = (const float4*)(g_ft + ((long)(b * NN + si[r][1])) * FC);
        const float4* f2 = (const float4*)(g_ft + ((long)(b * NN + si[r][2])) * FC);
        float4 a = f0[c4], bb = f1[c4], cc = f2[c4];
        float* dst = &sv[r][3 + c4 * 4];
        dst[0] = w0 * a.x + w1 * bb.x + w2 * cc.x;
        dst[1] = w0 * a.y + w1 * bb.y + w2 * cc.y;
        dst[2] = w0 * a.z + w1 * bb.z + w2 * cc.z;
        dst[3] = w0 * a.w + w1 * bb.w + w2 * cc.w;
    }
    __syncthreads();

    const float4* gr = g_grow[b];
#pragma unroll 2
    for (int r = 0; r < RPB; r++) {
        float* orow = out + ((long)(b * MQ + m0 + r)) * MQ;
        // segment A: columns [0, VCOLS): branchless dual-max, streaming stores
        for (int q = threadIdx.x; q < VCOLS / 4; q += 256) {
            float4 o;
            float* op = (float*)&o;
#pragma unroll
            for (int u = 0; u < 4; u++) {
                unsigned m = meta[q * 4 + u];
                op[u] = fmaxf(sv[r][m & 0xffff], sv[r][m >> 16]);
            }
            __stcs(((float4*)orow) + q, o);
        }
        // segment B: columns [VCOLS, MQ): batch-constant, streaming copy
        float4* od = (float4*)(orow + VCOLS);
        for (int q = threadIdx.x; q < GCOLS / 4; q += 256)
            __stcs(od + q, gr[q]);
    }
}

// ---------------- launch -----------------------------------------------------
extern "C" void kernel_launch(void* const* d_in, const int* in_sizes, int n_in,
                              void* d_out, int out_size) {
    const float* P  = (const float*)d_in[0];   // original_pts [B,3,N]
    const float* Q  = (const float*)d_in[1];   // query_pts    [B,3,M]
    const float* F1 = (const float*)d_in[2];   // local_feat1  [B,128,N]
    const float* F2 = (const float*)d_in[3];   // local_feat2  [B,256,N]
    const float* G  = (const float*)d_in[4];   // global_feats [B,1024]
    float* out = (float*)d_out;                // [B,M,M]

    mega_kernel<<<KNNB + TRB + GPB, 256>>>(P, Q, F1, F2, G);
    pool_kernel<<<BB * MQ / RPB, 256>>>(Q, G, out);
}

// round 15
// speedup vs baseline: 1.1003x; 1.0609x over previous
#include <cuda_runtime.h>
#include <math.h>

// Problem constants (fixed by setup_inputs)
#define BB 2
#define NN 16384
#define MQ 4096
#define C1 128
#define C2 256
#define FC 384          // feature channels (128 + 256)
#define VC 387          // 3 coords + 384 features (logical per-query channels)
#define GC 1024         // global feature channels
#define CT 1411         // total channels
#define VCOLS 1124      // output columns whose window touches per-query channels
#define GCOLS (MQ - VCOLS)   // 2972 columns depending only on global feats

#define TPTS 2048       // kNN smem tile points (32 KB of float4)
#define PPT (TPTS / 256)     // 8 points per thread per tile
#define KQW 2           // queries per warp (empirical optimum)
#define KWARPS 8        // warps per kNN block
#define KQB (KQW * KWARPS)   // 16 queries per block
#define FULL 0xffffffffu

#define SROWS 16        // output rows per segment-B block

// mega-kernel block ranges: [kNN | segB | transpose]
#define KNNB (BB * (MQ / KQB))                       // 512 kNN blocks
#define SEGB (BB * (MQ / SROWS))                     // 512 segment-B blocks
#define TRN  (NN / 32)                               // 512 transpose n-tiles
#define TRC  (FC / 32)                               // 12 transpose c-tiles
#define TRB  (TRN * TRC * BB)                        // 12288 transpose blocks

// ---------------- scratch (static device memory; no allocations) -------------
__device__ float  g_w [BB * MQ * 3];       // normalized Gaussian weights
__device__ int    g_i [BB * MQ * 3];       // final kNN indices
__device__ float  g_ft[(long)BB * NN * FC];// transposed features [b][n][c]

#define FINF __int_as_float(0x7f800000)

__device__ __forceinline__ void ins3(float t, int n,
                                     float& d0, float& d1, float& d2,
                                     int& i0, int& i1, int& i2) {
    if (t < d1) {
        d2 = d1; i2 = i1;
        if (t < d0) { d1 = d0; i1 = i0; d0 = t; i0 = n; }
        else        { d1 = t;  i1 = n; }
    } else { d2 = t; i2 = n; }
}

// ---------------- kernel A: mega (kNN | segB | transpose by block range) -----
union SmemU {
    float4 tile4[TPTS];          // kNN point tile (32 KB)
    float  t32[32][33];          // transpose tile
    float  grow[GCOLS];          // segment-B pooled global row (11.9 KB)
};

__global__ void __launch_bounds__(256)
mega_kernel(const float* __restrict__ P,  const float* __restrict__ Q,
            const float* __restrict__ F1, const float* __restrict__ F2,
            const float* __restrict__ G,  float* __restrict__ out) {
    __shared__ SmemU su;

    // ======================= path 1: kNN ===================================
    if (blockIdx.x < KNNB) {
        const int bpb = MQ / KQB;                 // 256 query-blocks per batch
        int b    = blockIdx.x / bpb;
        int q0   = (blockIdx.x % bpb) * KQB;
        int wid  = threadIdx.x >> 5;
        int lane = threadIdx.x & 31;

        float qx[KQW], qy[KQW], qz[KQW];
        int   mq[KQW];
#pragma unroll
        for (int g = 0; g < KQW; g++) {
            mq[g] = q0 + wid * KQW + g;
            qx[g] = Q[b * 3 * MQ + mq[g]];
            qy[g] = Q[b * 3 * MQ + MQ + mq[g]];
            qz[g] = Q[b * 3 * MQ + 2 * MQ + mq[g]];
        }

        float d0a[KQW], d1a[KQW], d2a[KQW];
        int   i0a[KQW], i1a[KQW], i2a[KQW];
#pragma unroll
        for (int g = 0; g < KQW; g++) {
            d0a[g] = FINF; d1a[g] = FINF; d2a[g] = FINF;
            i0a[g] = 0;    i1a[g] = 0;    i2a[g] = 0;
        }

        const float* Pb = P + b * 3 * NN;

        // prefetch tile 0 raw coordinates into registers
        float px[PPT], py[PPT], pz[PPT];
#pragma unroll
        for (int k = 0; k < PPT; k++) {
            int n = k * 256 + threadIdx.x;
            px[k] = Pb[n]; py[k] = Pb[NN + n]; pz[k] = Pb[2 * NN + n];
        }

#define RESCAN(tv, v, g)                                               \
    {                                                                  \
        unsigned bal = __ballot_sync(FULL, (tv) < d2a[g]);             \
        while (bal) {                                                  \
            int L = __ffs(bal) - 1; bal &= bal - 1;                    \
            float val = __shfl_sync(FULL, (tv), L);                    \
            if (val < d2a[g])                                          \
                ins3(val, tb + r + (v) * 32 + L,                       \
                     d0a[g], d1a[g], d2a[g], i0a[g], i1a[g], i2a[g]);  \
        }                                                              \
    }

        for (int tb = 0; tb < NN; tb += TPTS) {
            // store prefetched tile (preprocessed) to smem
#pragma unroll
            for (int k = 0; k < PPT; k++) {
                su.tile4[k * 256 + threadIdx.x] =
                    make_float4(-2.f * px[k], -2.f * py[k], -2.f * pz[k],
                                px[k] * px[k] + py[k] * py[k] + pz[k] * pz[k]);
            }
            __syncthreads();

            // prefetch NEXT tile raw coords (LDG latency hides under rounds)
            if (tb + TPTS < NN) {
#pragma unroll
                for (int k = 0; k < PPT; k++) {
                    int n = tb + TPTS + k * 256 + threadIdx.x;
                    px[k] = Pb[n]; py[k] = Pb[NN + n]; pz[k] = Pb[2 * NN + n];
                }
            }

            for (int r = 0; r < TPTS; r += 128) {      // 128 points per round
                float4 p0 = su.tile4[r + lane];
                float4 p1 = su.tile4[r + 32 + lane];
                float4 p2 = su.tile4[r + 64 + lane];
                float4 p3 = su.tile4[r + 96 + lane];
                float t0g[KQW], t1g[KQW], t2g[KQW], t3g[KQW];
                bool hit = false;
#pragma unroll
                for (int g = 0; g < KQW; g++) {
                    float t0 = fmaf(qz[g], p0.z, fmaf(qy[g], p0.y, fmaf(qx[g], p0.x, p0.w)));
                    float t1 = fmaf(qz[g], p1.z, fmaf(qy[g], p1.y, fmaf(qx[g], p1.x, p1.w)));
                    float t2 = fmaf(qz[g], p2.z, fmaf(qy[g], p2.y, fmaf(qx[g], p2.x, p2.w)));
                    float t3 = fmaf(qz[g], p3.z, fmaf(qy[g], p3.y, fmaf(qx[g], p3.x, p3.w)));
                    t0g[g] = t0; t1g[g] = t1; t2g[g] = t2; t3g[g] = t3;
                    float mn = fminf(fminf(t0, t1), fminf(t2, t3));
                    hit |= (mn < d2a[g]);
                }
                if (__any_sync(FULL, hit)) {           // one vote per round
#pragma unroll
                    for (int g = 0; g < KQW; g++) {
                        RESCAN(t0g[g], 0, g);
                        RESCAN(t1g[g], 1, g);
                        RESCAN(t2g[g], 2, g);
                        RESCAN(t3g[g], 3, g);
                    }
                }
            }
            __syncthreads();
        }
#undef RESCAN

        if (lane == 0) {
#pragma unroll
            for (int g = 0; g < KQW; g++) {
                int t = b * MQ + mq[g];
                float e1 = expf(-0.5f * (d1a[g] - d0a[g]));
                float e2 = expf(-0.5f * (d2a[g] - d0a[g]));
                float inv = 1.0f / (1.0f + e1 + e2);
                g_w[t * 3]     = inv;
                g_w[t * 3 + 1] = e1 * inv;
                g_w[t * 3 + 2] = e2 * inv;
                g_i[t * 3]     = i0a[g];
                g_i[t * 3 + 1] = i1a[g];
                g_i[t * 3 + 2] = i2a[g];
            }
        }
        return;
    }

    // ======================= path 2: output segment B (global-only cols) ====
    // columns [VCOLS, MQ) depend only on G: compute pooled row once in smem,
    // stream to SROWS output rows. Overlaps DRAM writes with kNN compute.
    if (blockIdx.x < KNNB + SEGB) {
        int t  = blockIdx.x - KNNB;
        int b  = t / (MQ / SROWS);
        int m0 = (t % (MQ / SROWS)) * SROWS;
        const float* Gb = G + b * GC;

        for (int j = threadIdx.x; j < GCOLS; j += 256) {
            int i  = VCOLS + j;
            int st = (i * CT) >> 12;
            int en = ((i + 1) * CT + 4095) >> 12;
            float a = __ldg(&Gb[st - VC]);
            if (en - st == 2) a = fmaxf(a, __ldg(&Gb[st + 1 - VC]));
            su.grow[j] = a;
        }
        __syncthreads();

        const float4* gr4 = (const float4*)su.grow;
#pragma unroll 2
        for (int r = 0; r < SROWS; r++) {
            float4* od = (float4*)(out + ((long)(b * MQ + m0 + r)) * MQ + VCOLS);
            for (int q = threadIdx.x; q < GCOLS / 4; q += 256)
                __stcs(od + q, gr4[q]);
        }
        return;
    }

    // ======================= path 3: feature transpose ======================
    {
        int t  = blockIdx.x - KNNB - SEGB;
        int n0 = (t % TRN) * 32;
        int cb = (t / TRN) % TRC;
        int b  = t / (TRN * TRC);
        const float* F;
        int C, c0, coff;
        if (cb < C1 / 32) { F = F1; C = C1; c0 = cb * 32;             coff = 0;  }
        else              { F = F2; C = C2; c0 = (cb - C1 / 32) * 32; coff = C1; }
        int tx = threadIdx.x & 31;
        int ty = threadIdx.x >> 5;

#pragma unroll
        for (int r = ty; r < 32; r += 8)
            su.t32[r][tx] = F[((long)(b * C + c0 + r)) * NN + n0 + tx];
        __syncthreads();
#pragma unroll
        for (int r = ty; r < 32; r += 8) {
            int n = n0 + r, c = c0 + tx;
            g_ft[((long)(b * NN + n)) * FC + coff + c] = su.t32[tx][r];
        }
    }
}

// ---------------- kernel B: fused interp + pool, segment A only -------------
#define RPB 8
__global__ void __launch_bounds__(256) pool_kernel(const float* __restrict__ Q,
                                                   const float* __restrict__ G,
                                                   float* __restrict__ out) {
    __shared__ float sv[RPB][VC + 1];   // [0..2]=coords, [3..386]=feat, [VC]=sg0
    __shared__ unsigned meta[VCOLS];    // st | (st2 << 16), branchless dual-max
    __shared__ float sw[RPB][3];
    __shared__ int   si[RPB][3];

    int blk = blockIdx.x;                 // 0 .. B*MQ/RPB - 1
    int b   = blk / (MQ / RPB);
    int m0  = (blk % (MQ / RPB)) * RPB;
    float sg0 = G[b * GC];                // only global channel reachable in i<VCOLS

    // precompute window metadata once per block (reused by all RPB rows)
    for (int i = threadIdx.x; i < VCOLS; i += 256) {
        unsigned st = (i * CT) >> 12;
        unsigned en = ((i + 1) * CT + 4095) >> 12;
        unsigned st2 = (en - st == 2) ? st + 1 : st;   // st2==VC handled via sv[.][VC]
        meta[i] = st | (st2 << 16);
    }
    if (threadIdx.x < RPB * 3) {
        int r = threadIdx.x / 3, k = threadIdx.x % 3;
        sw[r][k] = g_w[(b * MQ + m0 + r) * 3 + k];
        si[r][k] = g_i[(b * MQ + m0 + r) * 3 + k];
        sv[r][k] = Q[(b * 3 + k) * MQ + m0 + r];
    }
    if (threadIdx.x >= 32 && threadIdx.x < 32 + RPB)
        sv[threadIdx.x - 32][VC] = sg0;
    __syncthreads();

    // interpolation: RPB rows x 96 float4 tasks; gathers are contiguous 1536B rows
    for (int idx = threadIdx.x; idx < RPB * (FC / 4); idx += 256) {
        int r  = idx / (FC / 4);
        int c4 = idx % (FC / 4);
        float w0 = sw[r][0], w1 = sw[r][1], w2 = sw[r][2];
        const float4* f0 = (const float4*)(g_ft + ((long)(b * NN + si[r][0])) * FC);
        const float4* f1 = (const float4*)(g_ft + ((long)(b * NN + si[r][1])) * FC);
        const float4* f2 = (const float4*)(g_ft + ((long)(b * NN + si[r][2])) * FC);
        float4 a = f0[c4], bb = f1[c4], cc = f2[c4];
        float* dst = &sv[r][3 + c4 * 4];
        dst[0] = w0 * a.x + w1 * bb.x + w2 * cc.x;
        dst[1] = w0 * a.y + w1 * bb.y + w2 * cc.y;
        dst[2] = w0 * a.z + w1 * bb.z + w2 * cc.z;
        dst[3] = w0 * a.w + w1 * bb.w + w2 * cc.w;
    }
    __syncthreads();

#pragma unroll 2
    for (int r = 0; r < RPB; r++) {
        float* orow = out + ((long)(b * MQ + m0 + r)) * MQ;
        // segment A only: columns [0, VCOLS): branchless dual-max, streaming
        for (int q = threadIdx.x; q < VCOLS / 4; q += 256) {
            float4 o;
            float* op = (float*)&o;
#pragma unroll
            for (int u = 0; u < 4; u++) {
                unsigned m = meta[q * 4 + u];
                op[u] = fmaxf(sv[r][m & 0xffff], sv[r][m >> 16]);
            }
            __stcs(((float4*)orow) + q, o);
        }
    }
}

// ---------------- launch -----------------------------------------------------
extern "C" void kernel_launch(void* const* d_in, const int* in_sizes, int n_in,
                              void* d_out, int out_size) {
    const float* P  = (const float*)d_in[0];   // original_pts [B,3,N]
    const float* Q  = (const float*)d_in[1];   // query_pts    [B,3,M]
    const float* F1 = (const float*)d_in[2];   // local_feat1  [B,128,N]
    const float* F2 = (const float*)d_in[3];   // local_feat2  [B,256,N]
    const float* G  = (const float*)d_in[4];   // global_feats [B,1024]
    float* out = (float*)d_out;                // [B,M,M]

    mega_kernel<<<KNNB + SEGB + TRB, 256>>>(P, Q, F1, F2, G, out);
    pool_kernel<<<BB * MQ / RPB, 256>>>(Q, G, out);
}